// round 17
// baseline (speedup 1.0000x reference)
#include <cuda_runtime.h>
#include <cuda_bf16.h>
#include <math.h>
#include <stdint.h>

#define NEGV (-1e10f)
#define KSPAN 1024
#define KANT 50
#define GIDIM 512
#define HID 1000
#define MROWS (KSPAN*KANT)   // 51200
#define KA 1024              // gate GEMM K
#define KPA 576              // MLP K
#define NPAD 1024
#define NSLOTS 16

// mlp: 2-stage ring, 96-k chunks
#define MSTG_W 13312
#define MRING_B 106496
#define MLP_SMEM (MRING_B + 2112 + 512 + 128)
// sgemm: single-stage full-K tile 128x64, K-chunk 512
#define S1_AW 260            // words per row (512 bf16 + 4 pad)
#define S1_BOFF 33280        // B region word offset (128*260)
#define S1_SMEM 199680       // (128+64)*260*4

// ---------------- device scratch ----------------
__device__ __nv_bfloat16 d_gb[KSPAN*GIDIM];
__device__ __nv_bfloat16 d_gnb[KSPAN*GIDIM];
__device__ __nv_bfloat16 d_wcb[GIDIM*GIDIM];
__device__ __nv_bfloat16 d_projb[KSPAN*GIDIM];
__device__ float d_ant[KSPAN*KSPAN];
__device__ float d_bs[KSPAN*KANT];
__device__ int   d_bi[KSPAN*KANT];
__device__ __nv_bfloat16 d_A2[(size_t)MROWS*KPA];
__device__ __nv_bfloat16 d_B2t[(size_t)NPAD*KPA];
__device__ __nv_bfloat16 d_B1t[(size_t)NPAD*GIDIM];
__device__ __nv_bfloat16 d_Bjt[(size_t)NPAD*GIDIM];
__device__ __nv_bfloat16 d_Vjb[(size_t)KSPAN*NPAD];
__device__ __nv_bfloat16 d_wft[(size_t)GIDIM*KA];
__device__ __nv_bfloat16 d_gateA[(size_t)KSPAN*KA];
__device__ float d_Vi[(size_t)KSPAN*NPAD];
__device__ float d_Vg[8*NPAD];
__device__ float d_w2p[NPAD];
__device__ float d_b1p[NPAD];
__device__ float d_part[(size_t)NSLOTS*MROWS];
__device__ float d_an[KSPAN*GIDIM];

// ---------------- helpers ----------------
__device__ __forceinline__ uint32_t smem_u32(const void* p){
    uint32_t a; asm("{ .reg .u64 t; cvta.to.shared.u64 t, %1; cvt.u32.u64 %0, t; }" : "=r"(a) : "l"(p));
    return a;
}
__device__ __forceinline__ void cpasync16(uint32_t dst, const void* src){
    asm volatile("cp.async.cg.shared.global [%0], [%1], 16;\n" :: "r"(dst), "l"(src) : "memory");
}
#define WG(n) asm volatile("cp.async.wait_group %0;\n" :: "n"(n) : "memory")
#define CommitG() asm volatile("cp.async.commit_group;\n" ::: "memory")

// ---------------- merged prep (called 3x with base offsets) ----------------
__global__ void prep_master(int base, const float* __restrict__ g, const float* __restrict__ coarseW,
                            const float* __restrict__ W1, const float* __restrict__ Wf,
                            const float* __restrict__ b1, const float* __restrict__ W2,
                            const float* __restrict__ dist_e, const float* __restrict__ genre_e,
                            const float* __restrict__ spk_e){
    int b = base + blockIdx.x, t = threadIdx.x;
    if (b < 2048){
        int i = b*256 + t; d_gb[i] = __float2bfloat16(g[i]);
    } else if (b < 3072){
        int i = (b-2048)*256 + t; d_wcb[i] = __float2bfloat16(coarseW[i]);
    } else if (b < 5120){
        int idx = (b-3072)*256 + t;
        int n = idx >> 9, k = idx & 511;
        float a=0.f, bb=0.f, c=0.f;
        if (n < HID){
            a  = W1[(size_t)k*HID + n];
            bb = W1[(size_t)(512+k)*HID + n];
            c  = W1[(size_t)(1024+k)*HID + n];
        }
        d_B1t[(size_t)n*GIDIM + k] = __float2bfloat16(a);
        d_Bjt[(size_t)n*GIDIM + k] = __float2bfloat16(bb);
        d_B2t[(size_t)n*KPA + k]   = __float2bfloat16(c);
    } else if (b < 5376){
        int idx = (b-5120)*256 + t;
        int n = idx >> 6, c = idx & 63;
        float s = 0.f;
        if (c < 18 && n < HID){
            int bin = c>>1, lab = (c&1)+1;
            for (int k=0;k<20;k++) s += dist_e[bin*20+k]*W1[(size_t)(1536+k)*HID+n]
                                      + spk_e[lab*20+k]*W1[(size_t)(1576+k)*HID+n];
        }
        d_B2t[(size_t)n*KPA + 512 + c] = __float2bfloat16(s);
    } else if (b < 7424){
        int idx = (b-5376)*256 + t;
        int n = idx >> 10, k = idx & 1023;
        d_wft[idx] = __float2bfloat16(Wf[(size_t)k*GIDIM + n]);
    } else if (b < 7428){
        int n = (b-7424)*256 + t;
        d_w2p[n] = (n<HID)? W2[n]:0.f; d_b1p[n] = (n<HID)? b1[n]:0.f;
    } else {
        int idx = (b-7428)*256 + t;
        int row = idx >> 10, n = idx & 1023;
        float s = 0.f;
        if (n < HID)
            for (int k=0;k<20;k++) s += genre_e[row*20+k]*W1[(size_t)(1556+k)*HID+n];
        d_Vg[row*NPAD+n] = s;
    }
}

// ---------------- mlp consume macro (96-k chunk, stride 52 words) ----------------
#define CONSUME_STAGE6(wb)                                                                    \
    _Pragma("unroll")                                                                         \
    for (int ks=0; ks<6; ks++){                                                               \
        unsigned int af[2][4], bfr[8][2];                                                     \
        int aw = ks*8 + (lane&3);                                                             \
        _Pragma("unroll")                                                                     \
        for (int mi=0;mi<2;mi++){                                                             \
            int base = (wb) + (arow+mi*16)*52;                                                \
            af[mi][0]=sw[base+aw]; af[mi][1]=sw[base+416+aw];                                 \
            af[mi][2]=sw[base+aw+4]; af[mi][3]=sw[base+416+aw+4];                             \
        }                                                                                     \
        _Pragma("unroll")                                                                     \
        for (int ni=0;ni<8;ni++){                                                             \
            int base = (wb) + 6656 + (bb0+ni*8)*52 + aw;                                      \
            bfr[ni][0]=sw[base]; bfr[ni][1]=sw[base+4];                                       \
        }                                                                                     \
        _Pragma("unroll")                                                                     \
        for (int mi=0;mi<2;mi++)                                                              \
            _Pragma("unroll")                                                                 \
            for (int ni=0;ni<8;ni++)                                                          \
                asm volatile("mma.sync.aligned.m16n8k16.row.col.f32.bf16.bf16.f32 "           \
                    "{%0,%1,%2,%3},{%4,%5,%6,%7},{%8,%9},{%0,%1,%2,%3};\n"                    \
                    : "+f"(acc[mi][ni][0]), "+f"(acc[mi][ni][1]),                             \
                      "+f"(acc[mi][ni][2]), "+f"(acc[mi][ni][3])                              \
                    : "r"(af[mi][0]), "r"(af[mi][1]), "r"(af[mi][2]), "r"(af[mi][3]),         \
                      "r"(bfr[ni][0]), "r"(bfr[ni][1]));                                      \
    }

// ---------------- single-phase small GEMM: tile 128x64, K-chunk 512 ----------------
// modes: 1 ant+mask (K=512) | 3 gate (K=1024, 2 chunks) |
//        6 iter0: proj(bx<8)+Vi(8..23)+Vj(24..39) | 7 iter1: Vi(bx<16)+Vj(16..31)
__global__ void __launch_bounds__(256) sgemm(int mode, const __nv_bfloat16* __restrict__ A,
        const __nv_bfloat16* __restrict__ B, int Kdim,
        const float* __restrict__ aux0, const float* __restrict__ aux1,
        const int* __restrict__ auxi){
    extern __shared__ char dsm[];
    unsigned int* sw = (unsigned int*)dsm;
    int bx = blockIdx.x;
    const __nv_bfloat16* Bp = B;
    int sel = -1;
    int n0;
    if (mode == 6){
        sel = (bx < 8) ? 0 : (bx < 24 ? 1 : 2);
        Bp = (sel==0) ? d_wcb : (sel==1 ? d_B1t : d_Bjt);
        n0 = ((sel==0) ? bx : (sel==1 ? bx-8 : bx-24))*64;
    } else if (mode == 7){
        sel = (bx < 16) ? 1 : 2;
        Bp = (sel==1) ? d_B1t : d_Bjt;
        n0 = ((sel==1) ? bx : bx-16)*64;
    } else n0 = bx*64;
    int m0 = blockIdx.y*128;
    int tid = threadIdx.x, lane = tid&31, warp = tid>>5;
    int wm = warp&3, wn = warp>>2;
    int arow = wm*32 + (lane>>2);
    int bb0 = wn*32 + (lane>>2);
    float acc[2][4][4];
    #pragma unroll
    for (int a=0;a<2;a++)
        #pragma unroll
        for (int b=0;b<4;b++)
            #pragma unroll
            for (int c=0;c<4;c++) acc[a][b][c]=0.f;
    uint32_t sb = smem_u32(sw);
    int KC = Kdim >> 9;      // 1 or 2 chunks of 512
    for (int kc=0; kc<KC; kc++){
        int k0 = kc*512;
        // load A: 128 rows x 64 segs; B: 64 rows x 64 segs
        #pragma unroll
        for (int it=0; it<32; it++){
            int seg = tid + it*256;
            int row = seg >> 6, col = seg & 63;
            cpasync16(sb + row*1040 + col*16, A + (size_t)(m0+row)*Kdim + k0 + col*8);
        }
        #pragma unroll
        for (int it=0; it<16; it++){
            int seg = tid + it*256;
            int row = seg >> 6, col = seg & 63;
            cpasync16(sb + S1_BOFF*4 + row*1040 + col*16, Bp + (size_t)(n0+row)*Kdim + k0 + col*8);
        }
        CommitG();
        WG(0);
        __syncthreads();
        #pragma unroll 4
        for (int ks=0; ks<32; ks++){
            unsigned int af[2][4], bfr[4][2];
            int aw = ks*8 + (lane&3);
            #pragma unroll
            for (int mi=0;mi<2;mi++){
                int base = (arow+mi*16)*260;
                af[mi][0]=sw[base+aw]; af[mi][1]=sw[base+2080+aw];
                af[mi][2]=sw[base+aw+4]; af[mi][3]=sw[base+2080+aw+4];
            }
            #pragma unroll
            for (int ni=0;ni<4;ni++){
                int base = S1_BOFF + (bb0+ni*8)*260 + aw;
                bfr[ni][0]=sw[base]; bfr[ni][1]=sw[base+4];
            }
            #pragma unroll
            for (int mi=0;mi<2;mi++)
                #pragma unroll
                for (int ni=0;ni<4;ni++)
                    asm volatile("mma.sync.aligned.m16n8k16.row.col.f32.bf16.bf16.f32 "
                        "{%0,%1,%2,%3},{%4,%5,%6,%7},{%8,%9},{%0,%1,%2,%3};\n"
                        : "+f"(acc[mi][ni][0]), "+f"(acc[mi][ni][1]),
                          "+f"(acc[mi][ni][2]), "+f"(acc[mi][ni][3])
                        : "r"(af[mi][0]), "r"(af[mi][1]), "r"(af[mi][2]), "r"(af[mi][3]),
                          "r"(bfr[ni][0]), "r"(bfr[ni][1]));
        }
        if (kc+1 < KC) __syncthreads();
    }
    #pragma unroll
    for (int mi=0;mi<2;mi++)
        #pragma unroll
        for (int ni=0;ni<4;ni++)
            #pragma unroll
            for (int q=0;q<4;q++){
                int m = m0 + wm*32 + mi*16 + (lane>>2) + ((q>=2)?8:0);
                int n = n0 + wn*32 + ni*8 + (lane&3)*2 + (q&1);
                float v = acc[mi][ni][q];
                if (sel==0) d_projb[(size_t)m*GIDIM+n] = __float2bfloat16(v);
                else if (sel==1) d_Vi[(size_t)m*NPAD+n] = v + d_b1p[n] + d_Vg[auxi[m]*NPAD+n];
                else if (sel==2) d_Vjb[(size_t)m*NPAD+n] = __float2bfloat16(v);
                else if (mode==1){
                    v += aux0[m] + aux0[n];
                    if (n >= m) v += NEGV;
                    d_ant[(size_t)m*KSPAN+n] = v;
                } else {
                    float f = 1.f/(1.f+expf(-(v+aux0[n])));
                    float gv = aux1[(size_t)m*GIDIM+n];
                    float av = d_an[(size_t)m*GIDIM+n];
                    float o = (m==0)? gv : f*gv + (1.f-f)*av;
                    d_gnb[(size_t)m*GIDIM+n] = __float2bfloat16(o);
                }
            }
}

// ---------------- top-K bitonic ----------------
__global__ void topk_kernel(){
    int row = blockIdx.x;
    __shared__ unsigned long long sk[1024];
    for (int j=threadIdx.x; j<1024; j+=512){
        unsigned int b = __float_as_uint(d_ant[(size_t)row*KSPAN+j]);
        unsigned int asc = (b & 0x80000000u) ? ~b : (b | 0x80000000u);
        sk[j] = (((unsigned long long)(~asc))<<32) | (unsigned int)j;
    }
    __syncthreads();
    for (int k=2;k<=1024;k<<=1)
        for (int j=k>>1;j>0;j>>=1){
            for (int i=threadIdx.x;i<1024;i+=512){
                int ixj = i^j;
                if (ixj>i){
                    bool up = ((i&k)==0);
                    unsigned long long a=sk[i], b=sk[ixj];
                    if ((a>b)==up){ sk[i]=b; sk[ixj]=a; }
                }
            }
            __syncthreads();
        }
    if (threadIdx.x < KANT){
        int j = (int)(sk[threadIdx.x] & 0xffffffffu);
        d_bi[row*KANT+threadIdx.x] = j;
        d_bs[row*KANT+threadIdx.x] = d_ant[(size_t)row*KSPAN+j];
    }
}

// ---------------- build A2 = [gi*gj | onehot18 | 0pad] (576 cols) ----------------
__global__ void build_A(int it, const int* __restrict__ starts, const int* __restrict__ ends,
                        const int* __restrict__ sids){
    const __nv_bfloat16* g = it ? d_gnb : d_gb;
    int warp = threadIdx.x>>5, lane = threadIdx.x&31;
    int r = blockIdx.x*8 + warp;
    int i = r/KANT, j = d_bi[r];
    const uint4* gi4 = (const uint4*)(g + (size_t)i*GIDIM);
    const uint4* gj4 = (const uint4*)(g + (size_t)j*GIDIM);
    uint4 a0 = gi4[lane*2], a1 = gi4[lane*2+1];
    uint4 b0 = gj4[lane*2], b1 = gj4[lane*2+1];
    uint4 p0, p1;
    {
        const __nv_bfloat162* ap = (const __nv_bfloat162*)&a0;
        const __nv_bfloat162* bp = (const __nv_bfloat162*)&b0;
        __nv_bfloat162* pp = (__nv_bfloat162*)&p0;
        #pragma unroll
        for (int w=0; w<4; w++) pp[w] = __hmul2(ap[w], bp[w]);
        ap = (const __nv_bfloat162*)&a1; bp = (const __nv_bfloat162*)&b1;
        pp = (__nv_bfloat162*)&p1;
        #pragma unroll
        for (int w=0; w<4; w++) pp[w] = __hmul2(ap[w], bp[w]);
    }
    __nv_bfloat16* Ar = d_A2 + (size_t)r*KPA;
    ((uint4*)Ar)[lane*2]   = p0;
    ((uint4*)Ar)[lane*2+1] = p1;
    if (lane < 8){
        int d = ends[i]-starts[j];
        int bin = (d>1)+(d>2)+(d>3)+(d>4)+(d>8)+(d>16)+(d>32)+(d>64);
        int lab = (sids[i]==sids[j]) ? 1 : 2;
        int meta = bin*2 + lab - 1;
        uint4 z = make_uint4(0,0,0,0);
        int dd = meta - lane*8;
        if (dd >= 0 && dd < 8){
            unsigned int val = 0x3F80u << (16*(dd&1));
            ((unsigned int*)&z)[dd>>1] = val;
        }
        ((uint4*)(Ar+512))[lane] = z;
    }
}

// ---------------- MLP GEMM (K=576), 2-stage/96k + fused epilogue (r16-proven) ----------------
__global__ void __launch_bounds__(256,2) mlp_bf(){
    extern __shared__ char dsm[];
    unsigned int* sw = (unsigned int*)dsm;
    float* sVi = (float*)(dsm + MRING_B);
    float* sW2 = (float*)(dsm + MRING_B + 2112);
    unsigned char* iIdx = (unsigned char*)(dsm + MRING_B + 2624);
    int nt = blockIdx.x, n0 = nt*128, m0 = blockIdx.y*128;
    int tid = threadIdx.x, lane = tid&31, warp = tid>>5;
    int wm = warp&3, wn = warp>>2;
    int arow = wm*32 + (lane>>2);
    int bb0 = wn*64 + (lane>>2);
    int i0 = m0/KANT;
    if (tid < 128){
        iIdx[tid] = (unsigned char)((m0+tid)/KANT - i0);
        sW2[tid] = d_w2p[n0+tid];
    }
    {
        int rr = tid>>6, cc = tid&63;
        int row = min(i0+rr, KSPAN-1);
        *(float2*)(sVi + rr*132 + cc*2) = *(const float2*)(d_Vi + (size_t)row*NPAD + n0 + cc*2);
    }
    float acc[2][8][4];
    #pragma unroll
    for (int a=0;a<2;a++)
        #pragma unroll
        for (int b=0;b<8;b++)
            #pragma unroll
            for (int c=0;c<4;c++) acc[a][b][c]=0.f;
    auto issue = [&](int k){
        int st = k & 1;
        int k0 = k*96;
        uint32_t base = smem_u32(sw + st*MSTG_W);
        #pragma unroll
        for (int it=0; it<6; it++){
            int seg = tid + it*256;
            int row = seg/12, col = seg - row*12;
            cpasync16(base + row*208 + col*16,          d_A2  + (size_t)(m0+row)*KPA + k0 + col*8);
            cpasync16(base + 26624 + row*208 + col*16,  d_B2t + (size_t)(n0+row)*KPA + k0 + col*8);
        }
        CommitG();
    };
    issue(0);
    const int KT = KPA/96;   // 6
    for (int kt=0; kt<KT; kt++){
        WG(0);
        __syncthreads();
        if (kt+1 < KT) issue(kt+1);
        int wb = (kt&1)*MSTG_W;
        CONSUME_STAGE6(wb)
    }
    int slot = nt*2 + wn;
    #pragma unroll
    for (int mi=0;mi<2;mi++){
        int rA = wm*32 + mi*16 + (lane>>2), rB = rA+8;
        const float* viA = sVi + iIdx[rA]*132;
        const float* viB = sVi + iIdx[rB]*132;
        int jA = __ldg(d_bi + m0 + rA), jB = __ldg(d_bi + m0 + rB);
        const __nv_bfloat16* vjA = d_Vjb + (size_t)jA*NPAD + n0;
        const __nv_bfloat16* vjB = d_Vjb + (size_t)jB*NPAD + n0;
        float rs0 = 0.f, rs1 = 0.f;
        #pragma unroll
        for (int ni=0;ni<8;ni++){
            int nl = wn*64 + ni*8 + (lane&3)*2;
            float2 wv = *(const float2*)(sW2 + nl);
            float2 va = *(const float2*)(viA + nl);
            float2 vb = *(const float2*)(viB + nl);
            __nv_bfloat162 ja = *(const __nv_bfloat162*)(vjA + nl);
            __nv_bfloat162 jb = *(const __nv_bfloat162*)(vjB + nl);
            float h0 = acc[mi][ni][0] + va.x + __bfloat162float(ja.x);
            float h1 = acc[mi][ni][1] + va.y + __bfloat162float(ja.y);
            rs0 += fmaxf(h0,0.f)*wv.x + fmaxf(h1,0.f)*wv.y;
            float h2 = acc[mi][ni][2] + vb.x + __bfloat162float(jb.x);
            float h3 = acc[mi][ni][3] + vb.y + __bfloat162float(jb.y);
            rs1 += fmaxf(h2,0.f)*wv.x + fmaxf(h3,0.f)*wv.y;
        }
        rs0 += __shfl_xor_sync(0xffffffffu, rs0, 1);
        rs0 += __shfl_xor_sync(0xffffffffu, rs0, 2);
        rs1 += __shfl_xor_sync(0xffffffffu, rs1, 1);
        rs1 += __shfl_xor_sync(0xffffffffu, rs1, 2);
        if ((lane&3)==0){
            d_part[(size_t)slot*MROWS + m0 + rA] = rs0;
            d_part[(size_t)slot*MROWS + m0 + rB] = rs1;
        }
    }
}

// ---------------- refinement (+ fused part-reduce + gateA build) ----------------
__global__ void refine_kernel(const float* __restrict__ g, const float* __restrict__ b2){
    int i = blockIdx.x;
    int nv = min(i, KANT);
    __shared__ float p[KANT+1];
    __shared__ int ji[KANT];
    __shared__ float red[128];
    int tid = threadIdx.x;
    float val;
    if (tid==0) val = 0.f;
    else if (tid<=KANT){
        int kk = tid-1;
        if (kk < nv){
            float s = 0.f;
            #pragma unroll
            for (int t=0;t<NSLOTS;t++) s += d_part[(size_t)t*MROWS + i*KANT + kk];
            val = s + b2[0] + d_bs[i*KANT+kk];
        } else val = NEGV;
    } else val = NEGV;
    red[tid]=val; __syncthreads();
    for (int s=64;s>0;s>>=1){ if (tid<s) red[tid]=fmaxf(red[tid],red[tid+s]); __syncthreads(); }
    float mx = red[0]; __syncthreads();
    float e = (tid<=KANT) ? expf(val-mx) : 0.f;
    red[tid]=e; __syncthreads();
    for (int s=64;s>0;s>>=1){ if (tid<s) red[tid]+=red[tid+s]; __syncthreads(); }
    float sum = red[0];
    if (tid<=KANT) p[tid] = e/sum;
    if (tid<KANT) ji[tid] = d_bi[i*KANT+tid];
    __syncthreads();
    for (int d=tid; d<GIDIM; d+=128){
        float gv = g[(size_t)i*GIDIM+d];
        float a = p[0]*gv;
        for (int kk=0;kk<nv;kk++) a += p[kk+1]*g[(size_t)ji[kk]*GIDIM+d];
        d_an[(size_t)i*GIDIM+d] = a;
        d_gateA[(size_t)i*KA + d]         = __float2bfloat16(gv);
        d_gateA[(size_t)i*KA + GIDIM + d] = __float2bfloat16(a);
    }
}

// ---------------- final output (+ fused part-reduce) ----------------
__global__ void final_kernel(const float* __restrict__ b2, float* __restrict__ out){
    int idx = blockIdx.x*256 + threadIdx.x;
    if (idx >= KSPAN*(KANT+1)) return;
    int i = idx/(KANT+1), c = idx - i*(KANT+1);
    float v;
    if (c==0) v = 0.f;
    else {
        int kk = c-1;
        if (i==0) v = (kk==0)? 0.f : NEGV;
        else if (kk < min(i,KANT)){
            float s = 0.f;
            #pragma unroll
            for (int t=0;t<NSLOTS;t++) s += d_part[(size_t)t*MROWS + i*KANT + kk];
            v = s + b2[0] + d_bs[i*KANT+kk];
        } else v = NEGV;
    }
    out[idx] = v;
}

// ---------------- launch ----------------
extern "C" void kernel_launch(void* const* d_in, const int* in_sizes, int n_in,
                              void* d_out, int out_size){
    const float* g_i     = (const float*)d_in[0];
    const float* mention = (const float*)d_in[1];
    const float* dist_e  = (const float*)d_in[2];
    const float* genre_e = (const float*)d_in[3];
    const float* spk_e   = (const float*)d_in[4];
    const float* coarseW = (const float*)d_in[5];
    const float* W1      = (const float*)d_in[6];
    const float* b1      = (const float*)d_in[7];
    const float* W2      = (const float*)d_in[8];
    const float* b2      = (const float*)d_in[9];
    const float* Wf      = (const float*)d_in[10];
    const float* bfv     = (const float*)d_in[11];
    const int* starts    = (const int*)d_in[12];
    const int* ends      = (const int*)d_in[13];
    const int* gids      = (const int*)d_in[14];
    const int* sids      = (const int*)d_in[15];
    float* out = (float*)d_out;

    cudaFuncSetAttribute(sgemm, cudaFuncAttributeMaxDynamicSharedMemorySize, S1_SMEM);
    cudaFuncSetAttribute(mlp_bf, cudaFuncAttributeMaxDynamicSharedMemorySize, MLP_SMEM);

    prep_master<<<3072,256>>>(0,    g_i, coarseW, W1, Wf, b1, W2, dist_e, genre_e, spk_e);
    prep_master<<<2304,256>>>(3072, g_i, coarseW, W1, Wf, b1, W2, dist_e, genre_e, spk_e);
    prep_master<<<2084,256>>>(5376, g_i, coarseW, W1, Wf, b1, W2, dist_e, genre_e, spk_e);
    sgemm<<<dim3(40, 8),256,S1_SMEM>>>(6, d_gb, nullptr, GIDIM, nullptr, nullptr, gids);   // proj+Vi+Vj
    sgemm<<<dim3(16, 8),256,S1_SMEM>>>(1, d_projb, d_gb, GIDIM, mention, nullptr, nullptr);// ant
    topk_kernel<<<KSPAN,512>>>();
    build_A<<<MROWS/8,256>>>(0, starts, ends, sids);
    mlp_bf<<<dim3(NPAD/128, MROWS/128),256,MLP_SMEM>>>();
    refine_kernel<<<KSPAN,128>>>(g_i, b2);
    sgemm<<<dim3(8, 8),256,S1_SMEM>>>(3, d_gateA, d_wft, KA, bfv, g_i, nullptr);           // gate
    // iteration 1
    sgemm<<<dim3(32, 8),256,S1_SMEM>>>(7, d_gnb, nullptr, GIDIM, nullptr, nullptr, gids);  // Vi+Vj
    build_A<<<MROWS/8,256>>>(1, starts, ends, sids);
    mlp_bf<<<dim3(NPAD/128, MROWS/128),256,MLP_SMEM>>>();
    final_kernel<<<(KSPAN*(KANT+1)+255)/256,256>>>(b2, out);
}